// round 8
// baseline (speedup 1.0000x reference)
#include <cuda_runtime.h>
#include <math.h>

// ---------------------------------------------------------------------------
// Problem constants
// ---------------------------------------------------------------------------
#define NSAMP    524288      // 8192 rays * 64 samples

// combos: (0,1) (0,2) (0,3) (1,2) (1,3) (2,3)
// widths: 64,64,50,64,50,50  ->  W2: 128,128,100,128,100,100
// Interleaved plane-pair layout per combo: [Y][X][C=32][2] = (hi, lo)
#define TOTAL_PLANE_FLOATS 5603328   // 21.4 MB

__device__ float g_planes[TOTAL_PLANE_FLOATS];
__device__ float g_feats[64 * NSAMP];          // 134 MB, feature-major

// MLP weights in constant memory (45.5 KB < 64 KB bank).
__constant__ float cW1[64 * 64];
__constant__ float cW2[64 * 16];
__constant__ float cC1[31 * 64];
__constant__ float cC2[64 * 64];
__constant__ float cC3[64 * 3];

typedef unsigned long long ull;

// ---------------------------------------------------------------------------
// Packed dual-fp32 helpers (sm_100 f32x2 pipe; IEEE-identical per half)
// ---------------------------------------------------------------------------
__device__ __forceinline__ ull pack2(float f) {
    ull r;
    asm("mov.b64 %0, {%1, %1};" : "=l"(r) : "f"(f));
    return r;
}
__device__ __forceinline__ void ffma2(ull& d, ull a, ull b) {
    asm("fma.rn.f32x2 %0, %1, %2, %0;" : "+l"(d) : "l"(a), "l"(b));
}
__device__ __forceinline__ void mul2(ull& d, ull a, ull b) {
    asm("mul.rn.f32x2 %0, %1, %2;" : "=l"(d) : "l"(a), "l"(b));
}
__device__ __forceinline__ void unpack2(ull v, float& lo, float& hi) {
    asm("mov.b64 {%0, %1}, %2;" : "=f"(lo), "=f"(hi) : "l"(v));
}

// ---------------------------------------------------------------------------
// IDWT precompute, all 6 combos in one kernel.
// ---------------------------------------------------------------------------
template <int W, int W2, int OFF>
__device__ __forceinline__ void idwt_body(const float* __restrict__ yl,
                                          const float* __restrict__ yh,
                                          int idx) {
    if (idx >= 32 * 64 * W) return;

    int j0   = idx % W;
    int rest = idx / W;
    int i0   = rest & 63;
    int c    = rest >> 6;

    float a  = yl[(c * 64 + i0) * W + j0];
    float lh = yh[((c * 3 + 0) * 64 + i0) * W + j0];
    float hl = yh[((c * 3 + 1) * 64 + i0) * W + j0];
    float hh = yh[((c * 3 + 2) * 64 + i0) * W + j0];

    float ee = 0.5f * (a + lh + hl + hh);
    float eo = 0.5f * (a + lh - hl - hh);
    float oe = 0.5f * (a - lh + hl - hh);
    float oo = 0.5f * (a - lh - hl + hh);
    float lo = 0.5f * a;

    int fi = OFF + ((2 * i0) * W2 + 2 * j0) * 64 + 2 * c;
    *(float2*)(g_planes + fi)                = make_float2(ee, lo);
    *(float2*)(g_planes + fi + 64)           = make_float2(eo, lo);
    *(float2*)(g_planes + fi + W2 * 64)      = make_float2(oe, lo);
    *(float2*)(g_planes + fi + W2 * 64 + 64) = make_float2(oo, lo);
}

__global__ __launch_bounds__(256) void idwt_all(
    const float* __restrict__ yl0, const float* __restrict__ yh0,
    const float* __restrict__ yl1, const float* __restrict__ yh1,
    const float* __restrict__ yl2, const float* __restrict__ yh2,
    const float* __restrict__ yl3, const float* __restrict__ yh3,
    const float* __restrict__ yl4, const float* __restrict__ yh4,
    const float* __restrict__ yl5, const float* __restrict__ yh5) {
    int b = blockIdx.x;
    int t = threadIdx.x;
    if      (b <  512) idwt_body<64, 128,       0>(yl0, yh0, (b       ) * 256 + t);
    else if (b < 1024) idwt_body<64, 128, 1048576>(yl1, yh1, (b -  512) * 256 + t);
    else if (b < 1424) idwt_body<50, 100, 2097152>(yl2, yh2, (b - 1024) * 256 + t);
    else if (b < 1936) idwt_body<64, 128, 2916352>(yl3, yh3, (b - 1424) * 256 + t);
    else if (b < 2336) idwt_body<50, 100, 3964928>(yl4, yh4, (b - 1936) * 256 + t);
    else               idwt_body<50, 100, 4784128>(yl5, yh5, (b - 2336) * 256 + t);
}

// ---------------------------------------------------------------------------
// Gather helpers.
// Offset encoding: bits[0:24) = OFF + (y0*W2+x0)*64,
//                  bit 24 = (x1>x0), bit 25 = (y1>y0).
// ---------------------------------------------------------------------------
template <int W2, int OFF, int J, int K>
__device__ __forceinline__ void prep(const float p4[4], int& oenc,
                                     float& wy, float& wx) {
    float y = (p4[J] + 1.0f) * 0.5f * 127.0f;
    float x = (p4[K] + 1.0f) * 0.5f * (float)(W2 - 1);

    float yf = fminf(fmaxf(floorf(y), 0.0f), 127.0f);
    float xf = fminf(fmaxf(floorf(x), 0.0f), (float)(W2 - 1));
    int y0 = (int)yf, x0 = (int)xf;
    int y1 = min(y0 + 1, 127);
    int x1 = min(x0 + 1, W2 - 1);
    wy = fminf(fmaxf(y - yf, 0.0f), 1.0f);
    wx = fminf(fmaxf(x - xf, 0.0f), 1.0f);

    oenc = (OFF + (y0 * W2 + x0) * 64)
         | ((x1 > x0) ? (1 << 24) : 0)
         | ((y1 > y0) ? (1 << 25) : 0);
}

template <int DYC>   // DYC = W2*64
__device__ __forceinline__ void samp(int oenc, float wy, float wx,
                                     int lane2, ull& prod) {
    int base = (oenc & 0xFFFFFF) + lane2;
    int dx = ((oenc >> 24) & 1) << 6;
    int dy = (oenc & (1 << 25)) ? DYC : 0;

    float om_y = 1.0f - wy, om_x = 1.0f - wx;
    ull w00 = pack2(om_y * om_x);
    ull w01 = pack2(om_y * wx);
    ull w10 = pack2(wy * om_x);
    ull w11 = pack2(wy * wx);

    ull c00 = *(const ull*)(g_planes + base);
    ull c01 = *(const ull*)(g_planes + base + dx);
    ull c10 = *(const ull*)(g_planes + base + dy);
    ull c11 = *(const ull*)(g_planes + base + dy + dx);

    ull acc = 0ull;
    ffma2(acc, w00, c00);
    ffma2(acc, w01, c01);
    ffma2(acc, w10, c10);
    ffma2(acc, w11, c11);
    mul2(prod, prod, acc);
}

// ---------------------------------------------------------------------------
// Kernel A: gather -> feature-major scratch. 128 thr/blk, 34.5 KB dyn smem.
// ---------------------------------------------------------------------------
#define TSTRIDE 69
#define WARPBUF (32 * TSTRIDE)   // 2208 floats per warp

__global__ __launch_bounds__(128) void wf_gather(
    const float* __restrict__ pts, const float* __restrict__ ts) {

    extern __shared__ float wfbuf[];

    int lane = threadIdx.x & 31;
    int warp = threadIdx.x >> 5;
    int lane2 = 2 * lane;
    int n = blockIdx.x * 128 + threadIdx.x;

    float p4[4];
    p4[0] = pts[3*n + 0];
    p4[1] = pts[3*n + 1];
    p4[2] = pts[3*n + 2];
    p4[3] = ts[n >> 6] * 2.0f - 1.0f;

    int   oe0, oe1, oe2, oe3, oe4, oe5;
    float wy0, wy1, wy2, wy3, wy4, wy5;
    float wx0, wx1, wx2, wx3, wx4, wx5;
    prep<128,       0, 0, 1>(p4, oe0, wy0, wx0);
    prep<128, 1048576, 0, 2>(p4, oe1, wy1, wx1);
    prep<100, 2097152, 0, 3>(p4, oe2, wy2, wx2);
    prep<128, 2916352, 1, 2>(p4, oe3, wy3, wx3);
    prep<100, 3964928, 1, 3>(p4, oe4, wy4, wx4);
    prep<100, 4784128, 2, 3>(p4, oe5, wy5, wx5);

    float* wf = wfbuf + warp * WARPBUF;

#pragma unroll 1
    for (int s = 0; s < 32; s++) {
        ull prod = pack2(1.0f);

#define DO_COMBO(OE, WY, WX, DYC)                                  \
        {                                                          \
            int   o  = __shfl_sync(0xffffffffu, OE, s);            \
            float a_ = __shfl_sync(0xffffffffu, WY, s);            \
            float b_ = __shfl_sync(0xffffffffu, WX, s);            \
            samp<DYC>(o, a_, b_, lane2, prod);                     \
        }
        DO_COMBO(oe0, wy0, wx0, 8192)
        DO_COMBO(oe1, wy1, wx1, 8192)
        DO_COMBO(oe2, wy2, wx2, 6400)
        DO_COMBO(oe3, wy3, wx3, 8192)
        DO_COMBO(oe4, wy4, wx4, 6400)
        DO_COMBO(oe5, wy5, wx5, 6400)
#undef DO_COMBO

        float fh, fl;
        unpack2(prod, fh, fl);
        wf[s * TSTRIDE + lane]      = fh;
        wf[s * TSTRIDE + 34 + lane] = fl;
    }
    __syncwarp();

    const float* my = wf + lane * TSTRIDE;
#pragma unroll
    for (int j = 0; j < 32; j++)  g_feats[j * NSAMP + n] = my[j];
#pragma unroll
    for (int j = 32; j < 64; j++) g_feats[j * NSAMP + n] = my[j + 2];
}

// ---------------------------------------------------------------------------
// Half-layer helper: 32 outputs (16 packed acc) from NI inputs, const weights.
// Weight row stride 64; outputs [obase, obase+32).
// ---------------------------------------------------------------------------
template <int NI>
__device__ __forceinline__ void half_layer(const float* __restrict__ in,
                                           const float* __restrict__ cw,
                                           int obase, float* __restrict__ out,
                                           bool relu) {
    ull acc[16];
#pragma unroll
    for (int k = 0; k < 16; k++) acc[k] = 0ull;
#pragma unroll
    for (int i = 0; i < NI; i++) {
        ull fp = pack2(in[i]);
        const ulonglong2* wrow = (const ulonglong2*)(cw + i * 64 + obase);
#pragma unroll
        for (int og = 0; og < 8; og++) {
            ulonglong2 w = wrow[og];
            ffma2(acc[2*og],     fp, w.x);
            ffma2(acc[2*og + 1], fp, w.y);
        }
    }
#pragma unroll
    for (int k = 0; k < 16; k++) {
        float lo, hi;
        unpack2(acc[k], lo, hi);
        if (relu) { lo = fmaxf(lo, 0.f); hi = fmaxf(hi, 0.f); }
        out[obase + 2*k]     = lo;
        out[obase + 2*k + 1] = hi;
    }
}

// ---------------------------------------------------------------------------
// Kernel B: MLP chain, constant-memory weights, half-output passes.
// No shared memory.
// ---------------------------------------------------------------------------
__global__ __launch_bounds__(128) void wf_mlp(
    const float* __restrict__ dirs, float* __restrict__ outp) {

    int n = blockIdx.x * 128 + threadIdx.x;

    float fv[64];
#pragma unroll
    for (int i = 0; i < 64; i++) fv[i] = g_feats[i * NSAMP + n];

    // ---- MLP1: h = relu(fv @ Wsig1[64,64]) ----
    float h[64];
    half_layer<64>(fv, cW1, 0,  h, true);
    half_layer<64>(fv, cW1, 32, h, true);

    // ---- out = h @ Wsig2[64,16] ----
    float ov[16];
    {
        ull acc[8];
#pragma unroll
        for (int k = 0; k < 8; k++) acc[k] = 0ull;
#pragma unroll
        for (int i = 0; i < 64; i++) {
            ull fp = pack2(h[i]);
            const ulonglong2* wrow = (const ulonglong2*)(cW2 + i * 16);
#pragma unroll
            for (int og = 0; og < 4; og++) {
                ulonglong2 w = wrow[og];
                ffma2(acc[2*og],     fp, w.x);
                ffma2(acc[2*og + 1], fp, w.y);
            }
        }
#pragma unroll
        for (int k = 0; k < 8; k++) unpack2(acc[k], ov[2*k], ov[2*k+1]);
    }
    float density = expf(fminf(fmaxf(ov[15], -15.0f), 15.0f));

    // ---- SH degree-4 encoding ----
    int r = n >> 6;
    float dxv = dirs[3*r + 0], dyv = dirs[3*r + 1], dzv = dirs[3*r + 2];
    float inv = rsqrtf(dxv*dxv + dyv*dyv + dzv*dzv);
    float X = dxv * inv, Y = dyv * inv, Z = dzv * inv;
    float xx = X * X, yy = Y * Y, zz = Z * Z;

    float ci[31];
    ci[0]  = 0.28209479177387814f;
    ci[1]  = -0.4886025119029199f * Y;
    ci[2]  = 0.4886025119029199f * Z;
    ci[3]  = -0.4886025119029199f * X;
    ci[4]  = 1.0925484305920792f * X * Y;
    ci[5]  = -1.0925484305920792f * Y * Z;
    ci[6]  = 0.31539156525252005f * (3.0f * zz - 1.0f);
    ci[7]  = -1.0925484305920792f * X * Z;
    ci[8]  = 0.5462742152960396f * (xx - yy);
    ci[9]  = -0.5900435899266435f * Y * (3.0f * xx - yy);
    ci[10] = 2.890611442640554f * X * Y * Z;
    ci[11] = -0.4570457994644658f * Y * (5.0f * zz - 1.0f);
    ci[12] = 0.3731763325901154f * Z * (5.0f * zz - 3.0f);
    ci[13] = -0.4570457994644658f * X * (5.0f * zz - 1.0f);
    ci[14] = 1.445305721320277f * Z * (xx - yy);
    ci[15] = -0.5900435899266435f * X * (xx - 3.0f * yy);
#pragma unroll
    for (int g = 0; g < 15; g++) ci[16 + g] = ov[g];

    // ---- h2 = relu(ci @ Wc1[31,64]) ----
    float h2[64];
    half_layer<31>(ci, cC1, 0,  h2, true);
    half_layer<31>(ci, cC1, 32, h2, true);

    // ---- h3 = relu(h2 @ Wc2[64,64]) ----
    float h3[64];
    half_layer<64>(h2, cC2, 0,  h3, true);
    half_layer<64>(h2, cC2, 32, h3, true);

    // ---- rgb = sigmoid(h3 @ Wc3[64,3]) ----
    float r0 = 0.f, r1 = 0.f, r2 = 0.f;
#pragma unroll
    for (int i = 0; i < 64; i++) {
        float f = h3[i];
        r0 += f * cC3[i * 3 + 0];
        r1 += f * cC3[i * 3 + 1];
        r2 += f * cC3[i * 3 + 2];
    }

    float4 res;
    res.x = 1.0f / (1.0f + expf(-r0));
    res.y = 1.0f / (1.0f + expf(-r1));
    res.z = 1.0f / (1.0f + expf(-r2));
    res.w = density;
    *(float4*)(outp + 4 * n) = res;
}

// ---------------------------------------------------------------------------
// Launch
// ---------------------------------------------------------------------------
extern "C" void kernel_launch(void* const* d_in, const int* in_sizes, int n_in,
                              void* d_out, int out_size) {
    const float* pts  = (const float*)d_in[0];
    const float* dirs = (const float*)d_in[1];
    const float* ts   = (const float*)d_in[2];
    const float* yl0 = (const float*)d_in[3];  const float* yh0 = (const float*)d_in[4];
    const float* yl1 = (const float*)d_in[5];  const float* yh1 = (const float*)d_in[6];
    const float* yl2 = (const float*)d_in[7];  const float* yh2 = (const float*)d_in[8];
    const float* yl3 = (const float*)d_in[9];  const float* yh3 = (const float*)d_in[10];
    const float* yl4 = (const float*)d_in[11]; const float* yh4 = (const float*)d_in[12];
    const float* yl5 = (const float*)d_in[13]; const float* yh5 = (const float*)d_in[14];
    const float* Wsig1 = (const float*)d_in[15];
    const float* Wsig2 = (const float*)d_in[16];
    const float* Wc1   = (const float*)d_in[17];
    const float* Wc2   = (const float*)d_in[18];
    const float* Wc3   = (const float*)d_in[19];

    // Device-to-device async copies into constant bank (graph-capturable).
    cudaMemcpyToSymbolAsync(cW1, Wsig1, 64*64*sizeof(float), 0,
                            cudaMemcpyDeviceToDevice, 0);
    cudaMemcpyToSymbolAsync(cW2, Wsig2, 64*16*sizeof(float), 0,
                            cudaMemcpyDeviceToDevice, 0);
    cudaMemcpyToSymbolAsync(cC1, Wc1, 31*64*sizeof(float), 0,
                            cudaMemcpyDeviceToDevice, 0);
    cudaMemcpyToSymbolAsync(cC2, Wc2, 64*64*sizeof(float), 0,
                            cudaMemcpyDeviceToDevice, 0);
    cudaMemcpyToSymbolAsync(cC3, Wc3, 64*3*sizeof(float), 0,
                            cudaMemcpyDeviceToDevice, 0);

    idwt_all<<<2736, 256>>>(yl0, yh0, yl1, yh1, yl2, yh2,
                            yl3, yh3, yl4, yh4, yl5, yh5);

    size_t dyn = 4 * WARPBUF * sizeof(float);   // 34.5 KB dynamic
    wf_gather<<<NSAMP / 128, 128, dyn>>>(pts, ts);

    wf_mlp<<<NSAMP / 128, 128>>>(dirs, (float*)d_out);
}

// round 9
// speedup vs baseline: 1.1066x; 1.1066x over previous
#include <cuda_runtime.h>
#include <math.h>

// ---------------------------------------------------------------------------
// Problem constants
// ---------------------------------------------------------------------------
#define NSAMP    524288      // 8192 rays * 64 samples

// combos: (0,1) (0,2) (0,3) (1,2) (1,3) (2,3)
// widths: 64,64,50,64,50,50  ->  W2: 128,128,100,128,100,100
// Interleaved plane-pair layout per combo: [Y][X][C=32][2] = (hi, lo)
#define TOTAL_PLANE_FLOATS 5603328   // 21.4 MB

__device__ float g_planes[TOTAL_PLANE_FLOATS];
__device__ float g_feats[64 * NSAMP];          // 134 MB, feature-major

typedef unsigned long long ull;

// ---------------------------------------------------------------------------
// Packed dual-fp32 helpers (sm_100 f32x2 pipe; IEEE-identical per half)
// ---------------------------------------------------------------------------
__device__ __forceinline__ ull pack2(float f) {
    ull r;
    asm("mov.b64 %0, {%1, %1};" : "=l"(r) : "f"(f));
    return r;
}
__device__ __forceinline__ void ffma2(ull& d, ull a, ull b) {
    asm("fma.rn.f32x2 %0, %1, %2, %0;" : "+l"(d) : "l"(a), "l"(b));
}
__device__ __forceinline__ void mul2(ull& d, ull a, ull b) {
    asm("mul.rn.f32x2 %0, %1, %2;" : "=l"(d) : "l"(a), "l"(b));
}
__device__ __forceinline__ void unpack2(ull v, float& lo, float& hi) {
    asm("mov.b64 {%0, %1}, %2;" : "=f"(lo), "=f"(hi) : "l"(v));
}

// ---------------------------------------------------------------------------
// IDWT precompute, all 6 combos in one kernel.
// ---------------------------------------------------------------------------
template <int W, int W2, int OFF>
__device__ __forceinline__ void idwt_body(const float* __restrict__ yl,
                                          const float* __restrict__ yh,
                                          int idx) {
    if (idx >= 32 * 64 * W) return;

    int j0   = idx % W;
    int rest = idx / W;
    int i0   = rest & 63;
    int c    = rest >> 6;

    float a  = yl[(c * 64 + i0) * W + j0];
    float lh = yh[((c * 3 + 0) * 64 + i0) * W + j0];
    float hl = yh[((c * 3 + 1) * 64 + i0) * W + j0];
    float hh = yh[((c * 3 + 2) * 64 + i0) * W + j0];

    float ee = 0.5f * (a + lh + hl + hh);
    float eo = 0.5f * (a + lh - hl - hh);
    float oe = 0.5f * (a - lh + hl - hh);
    float oo = 0.5f * (a - lh - hl + hh);
    float lo = 0.5f * a;

    int fi = OFF + ((2 * i0) * W2 + 2 * j0) * 64 + 2 * c;
    *(float2*)(g_planes + fi)                = make_float2(ee, lo);
    *(float2*)(g_planes + fi + 64)           = make_float2(eo, lo);
    *(float2*)(g_planes + fi + W2 * 64)      = make_float2(oe, lo);
    *(float2*)(g_planes + fi + W2 * 64 + 64) = make_float2(oo, lo);
}

__global__ __launch_bounds__(256) void idwt_all(
    const float* __restrict__ yl0, const float* __restrict__ yh0,
    const float* __restrict__ yl1, const float* __restrict__ yh1,
    const float* __restrict__ yl2, const float* __restrict__ yh2,
    const float* __restrict__ yl3, const float* __restrict__ yh3,
    const float* __restrict__ yl4, const float* __restrict__ yh4,
    const float* __restrict__ yl5, const float* __restrict__ yh5) {
    int b = blockIdx.x;
    int t = threadIdx.x;
    if      (b <  512) idwt_body<64, 128,       0>(yl0, yh0, (b       ) * 256 + t);
    else if (b < 1024) idwt_body<64, 128, 1048576>(yl1, yh1, (b -  512) * 256 + t);
    else if (b < 1424) idwt_body<50, 100, 2097152>(yl2, yh2, (b - 1024) * 256 + t);
    else if (b < 1936) idwt_body<64, 128, 2916352>(yl3, yh3, (b - 1424) * 256 + t);
    else if (b < 2336) idwt_body<50, 100, 3964928>(yl4, yh4, (b - 1936) * 256 + t);
    else               idwt_body<50, 100, 4784128>(yl5, yh5, (b - 2336) * 256 + t);
}

// ---------------------------------------------------------------------------
// Gather helpers.
// Offset encoding: bits[0:24) = OFF + (y0*W2+x0)*64,
//                  bit 24 = (x1>x0), bit 25 = (y1>y0).
// ---------------------------------------------------------------------------
template <int W2, int OFF, int J, int K>
__device__ __forceinline__ void prep(const float p4[4], int& oenc,
                                     float& wy, float& wx) {
    float y = (p4[J] + 1.0f) * 0.5f * 127.0f;
    float x = (p4[K] + 1.0f) * 0.5f * (float)(W2 - 1);

    float yf = fminf(fmaxf(floorf(y), 0.0f), 127.0f);
    float xf = fminf(fmaxf(floorf(x), 0.0f), (float)(W2 - 1));
    int y0 = (int)yf, x0 = (int)xf;
    int y1 = min(y0 + 1, 127);
    int x1 = min(x0 + 1, W2 - 1);
    wy = fminf(fmaxf(y - yf, 0.0f), 1.0f);
    wx = fminf(fmaxf(x - xf, 0.0f), 1.0f);

    oenc = (OFF + (y0 * W2 + x0) * 64)
         | ((x1 > x0) ? (1 << 24) : 0)
         | ((y1 > y0) ? (1 << 25) : 0);
}

template <int DYC>   // DYC = W2*64
__device__ __forceinline__ void samp(int oenc, float wy, float wx,
                                     int lane2, ull& prod) {
    int base = (oenc & 0xFFFFFF) + lane2;
    int dx = ((oenc >> 24) & 1) << 6;
    int dy = (oenc & (1 << 25)) ? DYC : 0;

    float om_y = 1.0f - wy, om_x = 1.0f - wx;
    ull w00 = pack2(om_y * om_x);
    ull w01 = pack2(om_y * wx);
    ull w10 = pack2(wy * om_x);
    ull w11 = pack2(wy * wx);

    ull c00 = *(const ull*)(g_planes + base);
    ull c01 = *(const ull*)(g_planes + base + dx);
    ull c10 = *(const ull*)(g_planes + base + dy);
    ull c11 = *(const ull*)(g_planes + base + dy + dx);

    ull acc = 0ull;
    ffma2(acc, w00, c00);
    ffma2(acc, w01, c01);
    ffma2(acc, w10, c10);
    ffma2(acc, w11, c11);
    mul2(prod, prod, acc);
}

// ---------------------------------------------------------------------------
// Kernel A: gather -> feature-major scratch. 128 thr/blk, 34.5 KB dyn smem.
// ---------------------------------------------------------------------------
#define TSTRIDE 69
#define WARPBUF (32 * TSTRIDE)   // 2208 floats per warp

__global__ __launch_bounds__(128) void wf_gather(
    const float* __restrict__ pts, const float* __restrict__ ts) {

    extern __shared__ float wfbuf[];

    int lane = threadIdx.x & 31;
    int warp = threadIdx.x >> 5;
    int lane2 = 2 * lane;
    int n = blockIdx.x * 128 + threadIdx.x;

    float p4[4];
    p4[0] = pts[3*n + 0];
    p4[1] = pts[3*n + 1];
    p4[2] = pts[3*n + 2];
    p4[3] = ts[n >> 6] * 2.0f - 1.0f;

    int   oe0, oe1, oe2, oe3, oe4, oe5;
    float wy0, wy1, wy2, wy3, wy4, wy5;
    float wx0, wx1, wx2, wx3, wx4, wx5;
    prep<128,       0, 0, 1>(p4, oe0, wy0, wx0);
    prep<128, 1048576, 0, 2>(p4, oe1, wy1, wx1);
    prep<100, 2097152, 0, 3>(p4, oe2, wy2, wx2);
    prep<128, 2916352, 1, 2>(p4, oe3, wy3, wx3);
    prep<100, 3964928, 1, 3>(p4, oe4, wy4, wx4);
    prep<100, 4784128, 2, 3>(p4, oe5, wy5, wx5);

    float* wf = wfbuf + warp * WARPBUF;

#pragma unroll 1
    for (int s = 0; s < 32; s++) {
        ull prod = pack2(1.0f);

#define DO_COMBO(OE, WY, WX, DYC)                                  \
        {                                                          \
            int   o  = __shfl_sync(0xffffffffu, OE, s);            \
            float a_ = __shfl_sync(0xffffffffu, WY, s);            \
            float b_ = __shfl_sync(0xffffffffu, WX, s);            \
            samp<DYC>(o, a_, b_, lane2, prod);                     \
        }
        DO_COMBO(oe0, wy0, wx0, 8192)
        DO_COMBO(oe1, wy1, wx1, 8192)
        DO_COMBO(oe2, wy2, wx2, 6400)
        DO_COMBO(oe3, wy3, wx3, 8192)
        DO_COMBO(oe4, wy4, wx4, 6400)
        DO_COMBO(oe5, wy5, wx5, 6400)
#undef DO_COMBO

        float fh, fl;
        unpack2(prod, fh, fl);
        wf[s * TSTRIDE + lane]      = fh;
        wf[s * TSTRIDE + 34 + lane] = fl;
    }
    __syncwarp();

    const float* my = wf + lane * TSTRIDE;
#pragma unroll
    for (int j = 0; j < 32; j++)  g_feats[j * NSAMP + n] = my[j];
#pragma unroll
    for (int j = 32; j < 64; j++) g_feats[j * NSAMP + n] = my[j + 2];
}

// ---------------------------------------------------------------------------
// Half-layer: 32 outputs (16 packed acc) from NI inputs, SMEM weights.
// Weight row stride 64 floats; outputs [obase, obase+32).
// ---------------------------------------------------------------------------
template <int NI>
__device__ __forceinline__ void half_layer(const float* __restrict__ in,
                                           const float* __restrict__ sw,
                                           int obase, float* __restrict__ out,
                                           bool relu) {
    ull acc[16];
#pragma unroll
    for (int k = 0; k < 16; k++) acc[k] = 0ull;
#pragma unroll
    for (int i = 0; i < NI; i++) {
        ull fp = pack2(in[i]);
        const ulonglong2* wrow = (const ulonglong2*)(sw + i * 64 + obase);
#pragma unroll
        for (int og = 0; og < 8; og++) {
            ulonglong2 w = wrow[og];
            ffma2(acc[2*og],     fp, w.x);
            ffma2(acc[2*og + 1], fp, w.y);
        }
    }
#pragma unroll
    for (int k = 0; k < 16; k++) {
        float lo, hi;
        unpack2(acc[k], lo, hi);
        if (relu) { lo = fmaxf(lo, 0.f); hi = fmaxf(hi, 0.f); }
        out[obase + 2*k]     = lo;
        out[obase + 2*k + 1] = hi;
    }
}

// ---------------------------------------------------------------------------
// Kernel B: MLP chain, SMEM weights, half-output passes (low reg footprint).
// ---------------------------------------------------------------------------
__global__ __launch_bounds__(128) void wf_mlp(
    const float* __restrict__ dirs,
    const float* __restrict__ Wsig1, const float* __restrict__ Wsig2,
    const float* __restrict__ Wc1, const float* __restrict__ Wc2,
    const float* __restrict__ Wc3, float* __restrict__ outp) {

    __shared__ __align__(16) float sW1[64 * 64];
    __shared__ __align__(16) float sW2[64 * 16];
    __shared__ __align__(16) float sC1[32 * 64];
    __shared__ __align__(16) float sC2[64 * 64];
    __shared__ float sC3[64 * 3];

    for (int i = threadIdx.x; i < 64*64; i += 128) sW1[i] = Wsig1[i];
    for (int i = threadIdx.x; i < 64*16; i += 128) sW2[i] = Wsig2[i];
    for (int i = threadIdx.x; i < 31*64; i += 128) sC1[i] = Wc1[i];
    for (int i = threadIdx.x; i < 64*64; i += 128) sC2[i] = Wc2[i];
    for (int i = threadIdx.x; i < 64*3;  i += 128) sC3[i] = Wc3[i];
    __syncthreads();

    int n = blockIdx.x * 128 + threadIdx.x;

    float fv[64];
#pragma unroll
    for (int i = 0; i < 64; i++) fv[i] = g_feats[i * NSAMP + n];

    // ---- MLP1: h = relu(fv @ Wsig1[64,64]) ----
    float h[64];
    half_layer<64>(fv, sW1, 0,  h, true);
    half_layer<64>(fv, sW1, 32, h, true);

    // ---- out = h @ Wsig2[64,16] ----
    float ov[16];
    {
        ull acc[8];
#pragma unroll
        for (int k = 0; k < 8; k++) acc[k] = 0ull;
#pragma unroll
        for (int i = 0; i < 64; i++) {
            ull fp = pack2(h[i]);
            const ulonglong2* wrow = (const ulonglong2*)(sW2 + i * 16);
#pragma unroll
            for (int og = 0; og < 4; og++) {
                ulonglong2 w = wrow[og];
                ffma2(acc[2*og],     fp, w.x);
                ffma2(acc[2*og + 1], fp, w.y);
            }
        }
#pragma unroll
        for (int k = 0; k < 8; k++) unpack2(acc[k], ov[2*k], ov[2*k+1]);
    }
    float density = expf(fminf(fmaxf(ov[15], -15.0f), 15.0f));

    // ---- SH degree-4 encoding ----
    int r = n >> 6;
    float dxv = dirs[3*r + 0], dyv = dirs[3*r + 1], dzv = dirs[3*r + 2];
    float inv = rsqrtf(dxv*dxv + dyv*dyv + dzv*dzv);
    float X = dxv * inv, Y = dyv * inv, Z = dzv * inv;
    float xx = X * X, yy = Y * Y, zz = Z * Z;

    float ci[31];
    ci[0]  = 0.28209479177387814f;
    ci[1]  = -0.4886025119029199f * Y;
    ci[2]  = 0.4886025119029199f * Z;
    ci[3]  = -0.4886025119029199f * X;
    ci[4]  = 1.0925484305920792f * X * Y;
    ci[5]  = -1.0925484305920792f * Y * Z;
    ci[6]  = 0.31539156525252005f * (3.0f * zz - 1.0f);
    ci[7]  = -1.0925484305920792f * X * Z;
    ci[8]  = 0.5462742152960396f * (xx - yy);
    ci[9]  = -0.5900435899266435f * Y * (3.0f * xx - yy);
    ci[10] = 2.890611442640554f * X * Y * Z;
    ci[11] = -0.4570457994644658f * Y * (5.0f * zz - 1.0f);
    ci[12] = 0.3731763325901154f * Z * (5.0f * zz - 3.0f);
    ci[13] = -0.4570457994644658f * X * (5.0f * zz - 1.0f);
    ci[14] = 1.445305721320277f * Z * (xx - yy);
    ci[15] = -0.5900435899266435f * X * (xx - 3.0f * yy);
#pragma unroll
    for (int g = 0; g < 15; g++) ci[16 + g] = ov[g];

    // ---- h2 = relu(ci @ Wc1[31,64]) ----
    float h2[64];
    half_layer<31>(ci, sC1, 0,  h2, true);
    half_layer<31>(ci, sC1, 32, h2, true);

    // ---- h3 = relu(h2 @ Wc2[64,64]) ----
    float h3[64];
    half_layer<64>(h2, sC2, 0,  h3, true);
    half_layer<64>(h2, sC2, 32, h3, true);

    // ---- rgb = sigmoid(h3 @ Wc3[64,3]) ----
    float r0 = 0.f, r1 = 0.f, r2 = 0.f;
#pragma unroll
    for (int i = 0; i < 64; i++) {
        float f = h3[i];
        r0 += f * sC3[i * 3 + 0];
        r1 += f * sC3[i * 3 + 1];
        r2 += f * sC3[i * 3 + 2];
    }

    float4 res;
    res.x = 1.0f / (1.0f + expf(-r0));
    res.y = 1.0f / (1.0f + expf(-r1));
    res.z = 1.0f / (1.0f + expf(-r2));
    res.w = density;
    *(float4*)(outp + 4 * n) = res;
}

// ---------------------------------------------------------------------------
// Launch
// ---------------------------------------------------------------------------
extern "C" void kernel_launch(void* const* d_in, const int* in_sizes, int n_in,
                              void* d_out, int out_size) {
    const float* pts  = (const float*)d_in[0];
    const float* dirs = (const float*)d_in[1];
    const float* ts   = (const float*)d_in[2];
    const float* yl0 = (const float*)d_in[3];  const float* yh0 = (const float*)d_in[4];
    const float* yl1 = (const float*)d_in[5];  const float* yh1 = (const float*)d_in[6];
    const float* yl2 = (const float*)d_in[7];  const float* yh2 = (const float*)d_in[8];
    const float* yl3 = (const float*)d_in[9];  const float* yh3 = (const float*)d_in[10];
    const float* yl4 = (const float*)d_in[11]; const float* yh4 = (const float*)d_in[12];
    const float* yl5 = (const float*)d_in[13]; const float* yh5 = (const float*)d_in[14];
    const float* Wsig1 = (const float*)d_in[15];
    const float* Wsig2 = (const float*)d_in[16];
    const float* Wc1   = (const float*)d_in[17];
    const float* Wc2   = (const float*)d_in[18];
    const float* Wc3   = (const float*)d_in[19];

    idwt_all<<<2736, 256>>>(yl0, yh0, yl1, yh1, yl2, yh2,
                            yl3, yh3, yl4, yh4, yl5, yh5);

    size_t dyn = 4 * WARPBUF * sizeof(float);   // 34.5 KB dynamic
    wf_gather<<<NSAMP / 128, 128, dyn>>>(pts, ts);

    wf_mlp<<<NSAMP / 128, 128>>>(dirs, Wsig1, Wsig2, Wc1, Wc2, Wc3,
                                 (float*)d_out);
}

// round 10
// speedup vs baseline: 1.1813x; 1.0675x over previous
#include <cuda_runtime.h>
#include <cuda_fp16.h>
#include <math.h>

// ---------------------------------------------------------------------------
// Problem constants
// ---------------------------------------------------------------------------
#define NSAMP    524288      // 8192 rays * 64 samples

// combos: (0,1) (0,2) (0,3) (1,2) (1,3) (2,3)
// widths: 64,64,50,64,50,50  ->  W2: 128,128,100,128,100,100
// Interleaved plane-pair layout per combo: [Y][X][C=32][2] = (hi, lo), fp16.
#define TOTAL_PLANE_ELEMS 5603328   // halves: 11.2 MB

__device__ __half g_planes[TOTAL_PLANE_ELEMS];
__device__ float  g_feats[64 * NSAMP];          // 134 MB, feature-major

typedef unsigned long long ull;

// ---------------------------------------------------------------------------
// Packed dual-fp32 helpers (sm_100 f32x2 pipe; IEEE-identical per half)
// ---------------------------------------------------------------------------
__device__ __forceinline__ ull pack2(float f) {
    ull r;
    asm("mov.b64 %0, {%1, %1};" : "=l"(r) : "f"(f));
    return r;
}
__device__ __forceinline__ void ffma2(ull& d, ull a, ull b) {
    asm("fma.rn.f32x2 %0, %1, %2, %0;" : "+l"(d) : "l"(a), "l"(b));
}
__device__ __forceinline__ void mul2(ull& d, ull a, ull b) {
    asm("mul.rn.f32x2 %0, %1, %2;" : "=l"(d) : "l"(a), "l"(b));
}
__device__ __forceinline__ void unpack2(ull v, float& lo, float& hi) {
    asm("mov.b64 {%0, %1}, %2;" : "=f"(lo), "=f"(hi) : "l"(v));
}
// half2 (packed in u32) -> packed f32x2 in u64
__device__ __forceinline__ ull h2f2(unsigned v) {
    __half2 h = *(__half2*)&v;
    float2 f = __half22float2(h);
    ull r;
    asm("mov.b64 %0, {%1, %2};" : "=l"(r) : "f"(f.x), "f"(f.y));
    return r;
}

// ---------------------------------------------------------------------------
// IDWT precompute, all 6 combos in one kernel; writes fp16 (hi,lo) pairs.
// ---------------------------------------------------------------------------
template <int W, int W2, int OFF>
__device__ __forceinline__ void idwt_body(const float* __restrict__ yl,
                                          const float* __restrict__ yh,
                                          int idx) {
    if (idx >= 32 * 64 * W) return;

    int j0   = idx % W;
    int rest = idx / W;
    int i0   = rest & 63;
    int c    = rest >> 6;

    float a  = yl[(c * 64 + i0) * W + j0];
    float lh = yh[((c * 3 + 0) * 64 + i0) * W + j0];
    float hl = yh[((c * 3 + 1) * 64 + i0) * W + j0];
    float hh = yh[((c * 3 + 2) * 64 + i0) * W + j0];

    float ee = 0.5f * (a + lh + hl + hh);
    float eo = 0.5f * (a + lh - hl - hh);
    float oe = 0.5f * (a - lh + hl - hh);
    float oo = 0.5f * (a - lh - hl + hh);
    float lo = 0.5f * a;

    int fi = OFF + ((2 * i0) * W2 + 2 * j0) * 64 + 2 * c;   // element index
    __half* gp = g_planes;
    *(__half2*)(gp + fi)                = __floats2half2_rn(ee, lo);
    *(__half2*)(gp + fi + 64)           = __floats2half2_rn(eo, lo);
    *(__half2*)(gp + fi + W2 * 64)      = __floats2half2_rn(oe, lo);
    *(__half2*)(gp + fi + W2 * 64 + 64) = __floats2half2_rn(oo, lo);
}

__global__ __launch_bounds__(256) void idwt_all(
    const float* __restrict__ yl0, const float* __restrict__ yh0,
    const float* __restrict__ yl1, const float* __restrict__ yh1,
    const float* __restrict__ yl2, const float* __restrict__ yh2,
    const float* __restrict__ yl3, const float* __restrict__ yh3,
    const float* __restrict__ yl4, const float* __restrict__ yh4,
    const float* __restrict__ yl5, const float* __restrict__ yh5) {
    int b = blockIdx.x;
    int t = threadIdx.x;
    if      (b <  512) idwt_body<64, 128,       0>(yl0, yh0, (b       ) * 256 + t);
    else if (b < 1024) idwt_body<64, 128, 1048576>(yl1, yh1, (b -  512) * 256 + t);
    else if (b < 1424) idwt_body<50, 100, 2097152>(yl2, yh2, (b - 1024) * 256 + t);
    else if (b < 1936) idwt_body<64, 128, 2916352>(yl3, yh3, (b - 1424) * 256 + t);
    else if (b < 2336) idwt_body<50, 100, 3964928>(yl4, yh4, (b - 1936) * 256 + t);
    else               idwt_body<50, 100, 4784128>(yl5, yh5, (b - 2336) * 256 + t);
}

// ---------------------------------------------------------------------------
// Gather helpers.
// Offset encoding: bits[0:24) = OFF + (y0*W2+x0)*64 (element units),
//                  bit 24 = (x1>x0), bit 25 = (y1>y0).
// ---------------------------------------------------------------------------
template <int W2, int OFF, int J, int K>
__device__ __forceinline__ void prep(const float p4[4], int& oenc,
                                     float& wy, float& wx) {
    float y = (p4[J] + 1.0f) * 0.5f * 127.0f;
    float x = (p4[K] + 1.0f) * 0.5f * (float)(W2 - 1);

    float yf = fminf(fmaxf(floorf(y), 0.0f), 127.0f);
    float xf = fminf(fmaxf(floorf(x), 0.0f), (float)(W2 - 1));
    int y0 = (int)yf, x0 = (int)xf;
    int y1 = min(y0 + 1, 127);
    int x1 = min(x0 + 1, W2 - 1);
    wy = fminf(fmaxf(y - yf, 0.0f), 1.0f);
    wx = fminf(fmaxf(x - xf, 0.0f), 1.0f);

    oenc = (OFF + (y0 * W2 + x0) * 64)
         | ((x1 > x0) ? (1 << 24) : 0)
         | ((y1 > y0) ? (1 << 25) : 0);
}

template <int DYC>   // DYC = W2*64 (element units)
__device__ __forceinline__ void samp(int oenc, float wy, float wx,
                                     int lane2, ull& prod) {
    int base = (oenc & 0xFFFFFF) + lane2;
    int dx = ((oenc >> 24) & 1) << 6;
    int dy = (oenc & (1 << 25)) ? DYC : 0;

    float om_y = 1.0f - wy, om_x = 1.0f - wx;
    ull w00 = pack2(om_y * om_x);
    ull w01 = pack2(om_y * wx);
    ull w10 = pack2(wy * om_x);
    ull w11 = pack2(wy * wx);

    const __half* gp = g_planes;
    unsigned v00 = *(const unsigned*)(gp + base);
    unsigned v01 = *(const unsigned*)(gp + base + dx);
    unsigned v10 = *(const unsigned*)(gp + base + dy);
    unsigned v11 = *(const unsigned*)(gp + base + dy + dx);

    ull acc = 0ull;
    ffma2(acc, w00, h2f2(v00));
    ffma2(acc, w01, h2f2(v01));
    ffma2(acc, w10, h2f2(v10));
    ffma2(acc, w11, h2f2(v11));
    mul2(prod, prod, acc);
}

// ---------------------------------------------------------------------------
// Kernel A: gather -> feature-major scratch. 128 thr/blk, 34.5 KB dyn smem.
// ---------------------------------------------------------------------------
#define TSTRIDE 69
#define WARPBUF (32 * TSTRIDE)   // 2208 floats per warp

__global__ __launch_bounds__(128) void wf_gather(
    const float* __restrict__ pts, const float* __restrict__ ts) {

    extern __shared__ float wfbuf[];

    int lane = threadIdx.x & 31;
    int warp = threadIdx.x >> 5;
    int lane2 = 2 * lane;
    int n = blockIdx.x * 128 + threadIdx.x;

    float p4[4];
    p4[0] = pts[3*n + 0];
    p4[1] = pts[3*n + 1];
    p4[2] = pts[3*n + 2];
    p4[3] = ts[n >> 6] * 2.0f - 1.0f;

    int   oe0, oe1, oe2, oe3, oe4, oe5;
    float wy0, wy1, wy2, wy3, wy4, wy5;
    float wx0, wx1, wx2, wx3, wx4, wx5;
    prep<128,       0, 0, 1>(p4, oe0, wy0, wx0);
    prep<128, 1048576, 0, 2>(p4, oe1, wy1, wx1);
    prep<100, 2097152, 0, 3>(p4, oe2, wy2, wx2);
    prep<128, 2916352, 1, 2>(p4, oe3, wy3, wx3);
    prep<100, 3964928, 1, 3>(p4, oe4, wy4, wx4);
    prep<100, 4784128, 2, 3>(p4, oe5, wy5, wx5);

    float* wf = wfbuf + warp * WARPBUF;

#pragma unroll 1
    for (int s = 0; s < 32; s++) {
        ull prod = pack2(1.0f);

#define DO_COMBO(OE, WY, WX, DYC)                                  \
        {                                                          \
            int   o  = __shfl_sync(0xffffffffu, OE, s);            \
            float a_ = __shfl_sync(0xffffffffu, WY, s);            \
            float b_ = __shfl_sync(0xffffffffu, WX, s);            \
            samp<DYC>(o, a_, b_, lane2, prod);                     \
        }
        DO_COMBO(oe0, wy0, wx0, 8192)
        DO_COMBO(oe1, wy1, wx1, 8192)
        DO_COMBO(oe2, wy2, wx2, 6400)
        DO_COMBO(oe3, wy3, wx3, 8192)
        DO_COMBO(oe4, wy4, wx4, 6400)
        DO_COMBO(oe5, wy5, wx5, 6400)
#undef DO_COMBO

        float fh, fl;
        unpack2(prod, fh, fl);
        wf[s * TSTRIDE + lane]      = fh;
        wf[s * TSTRIDE + 34 + lane] = fl;
    }
    __syncwarp();

    const float* my = wf + lane * TSTRIDE;
#pragma unroll
    for (int j = 0; j < 32; j++)  g_feats[j * NSAMP + n] = my[j];
#pragma unroll
    for (int j = 32; j < 64; j++) g_feats[j * NSAMP + n] = my[j + 2];
}

// ---------------------------------------------------------------------------
// Kernel B: MLP chain with packed f32x2 FFMA. Static smem weights (44.75 KB).
// (R6 full-layer form — best measured variant.)
// ---------------------------------------------------------------------------
__global__ __launch_bounds__(128) void wf_mlp(
    const float* __restrict__ dirs,
    const float* __restrict__ Wsig1, const float* __restrict__ Wsig2,
    const float* __restrict__ Wc1, const float* __restrict__ Wc2,
    const float* __restrict__ Wc3, float* __restrict__ outp) {

    __shared__ __align__(16) float sW1[64 * 64];
    __shared__ __align__(16) float sW2[64 * 16];
    __shared__ __align__(16) float sC1[32 * 64];
    __shared__ __align__(16) float sC2[64 * 64];
    __shared__ float sC3[64 * 3];

    for (int i = threadIdx.x; i < 64*64; i += 128) sW1[i] = Wsig1[i];
    for (int i = threadIdx.x; i < 64*16; i += 128) sW2[i] = Wsig2[i];
    for (int i = threadIdx.x; i < 31*64; i += 128) sC1[i] = Wc1[i];
    for (int i = threadIdx.x; i < 64*64; i += 128) sC2[i] = Wc2[i];
    for (int i = threadIdx.x; i < 64*3;  i += 128) sC3[i] = Wc3[i];
    __syncthreads();

    int n = blockIdx.x * 128 + threadIdx.x;

    float fv[64];
#pragma unroll
    for (int i = 0; i < 64; i++) fv[i] = g_feats[i * NSAMP + n];

    // ---- MLP1: h = relu(fv @ Wsig1[64,64]) ----
    float h[64];
    {
        ull acc[32];
#pragma unroll
        for (int k = 0; k < 32; k++) acc[k] = 0ull;
#pragma unroll
        for (int i = 0; i < 64; i++) {
            ull fp = pack2(fv[i]);
            const ulonglong2* wrow = (const ulonglong2*)(sW1 + i * 64);
#pragma unroll
            for (int og = 0; og < 16; og++) {
                ulonglong2 w = wrow[og];
                ffma2(acc[2*og],     fp, w.x);
                ffma2(acc[2*og + 1], fp, w.y);
            }
        }
#pragma unroll
        for (int k = 0; k < 32; k++) {
            float lo, hi;
            unpack2(acc[k], lo, hi);
            h[2*k]   = fmaxf(lo, 0.f);
            h[2*k+1] = fmaxf(hi, 0.f);
        }
    }

    // ---- out = h @ Wsig2[64,16] ----
    float ov[16];
    {
        ull acc[8];
#pragma unroll
        for (int k = 0; k < 8; k++) acc[k] = 0ull;
#pragma unroll
        for (int i = 0; i < 64; i++) {
            ull fp = pack2(h[i]);
            const ulonglong2* wrow = (const ulonglong2*)(sW2 + i * 16);
#pragma unroll
            for (int og = 0; og < 4; og++) {
                ulonglong2 w = wrow[og];
                ffma2(acc[2*og],     fp, w.x);
                ffma2(acc[2*og + 1], fp, w.y);
            }
        }
#pragma unroll
        for (int k = 0; k < 8; k++) unpack2(acc[k], ov[2*k], ov[2*k+1]);
    }
    float density = expf(fminf(fmaxf(ov[15], -15.0f), 15.0f));

    // ---- SH degree-4 encoding ----
    int r = n >> 6;
    float dxv = dirs[3*r + 0], dyv = dirs[3*r + 1], dzv = dirs[3*r + 2];
    float inv = rsqrtf(dxv*dxv + dyv*dyv + dzv*dzv);
    float X = dxv * inv, Y = dyv * inv, Z = dzv * inv;
    float xx = X * X, yy = Y * Y, zz = Z * Z;

    float ci[31];
    ci[0]  = 0.28209479177387814f;
    ci[1]  = -0.4886025119029199f * Y;
    ci[2]  = 0.4886025119029199f * Z;
    ci[3]  = -0.4886025119029199f * X;
    ci[4]  = 1.0925484305920792f * X * Y;
    ci[5]  = -1.0925484305920792f * Y * Z;
    ci[6]  = 0.31539156525252005f * (3.0f * zz - 1.0f);
    ci[7]  = -1.0925484305920792f * X * Z;
    ci[8]  = 0.5462742152960396f * (xx - yy);
    ci[9]  = -0.5900435899266435f * Y * (3.0f * xx - yy);
    ci[10] = 2.890611442640554f * X * Y * Z;
    ci[11] = -0.4570457994644658f * Y * (5.0f * zz - 1.0f);
    ci[12] = 0.3731763325901154f * Z * (5.0f * zz - 3.0f);
    ci[13] = -0.4570457994644658f * X * (5.0f * zz - 1.0f);
    ci[14] = 1.445305721320277f * Z * (xx - yy);
    ci[15] = -0.5900435899266435f * X * (xx - 3.0f * yy);
#pragma unroll
    for (int g = 0; g < 15; g++) ci[16 + g] = ov[g];

    // ---- h2 = relu(ci @ Wc1[31,64]) ----
    float h2[64];
    {
        ull acc[32];
#pragma unroll
        for (int k = 0; k < 32; k++) acc[k] = 0ull;
#pragma unroll
        for (int i = 0; i < 31; i++) {
            ull fp = pack2(ci[i]);
            const ulonglong2* wrow = (const ulonglong2*)(sC1 + i * 64);
#pragma unroll
            for (int og = 0; og < 16; og++) {
                ulonglong2 w = wrow[og];
                ffma2(acc[2*og],     fp, w.x);
                ffma2(acc[2*og + 1], fp, w.y);
            }
        }
#pragma unroll
        for (int k = 0; k < 32; k++) {
            float lo, hi;
            unpack2(acc[k], lo, hi);
            h2[2*k]   = fmaxf(lo, 0.f);
            h2[2*k+1] = fmaxf(hi, 0.f);
        }
    }

    // ---- h3 = relu(h2 @ Wc2[64,64]) ----
    float h3[64];
    {
        ull acc[32];
#pragma unroll
        for (int k = 0; k < 32; k++) acc[k] = 0ull;
#pragma unroll
        for (int i = 0; i < 64; i++) {
            ull fp = pack2(h2[i]);
            const ulonglong2* wrow = (const ulonglong2*)(sC2 + i * 64);
#pragma unroll
            for (int og = 0; og < 16; og++) {
                ulonglong2 w = wrow[og];
                ffma2(acc[2*og],     fp, w.x);
                ffma2(acc[2*og + 1], fp, w.y);
            }
        }
#pragma unroll
        for (int k = 0; k < 32; k++) {
            float lo, hi;
            unpack2(acc[k], lo, hi);
            h3[2*k]   = fmaxf(lo, 0.f);
            h3[2*k+1] = fmaxf(hi, 0.f);
        }
    }

    // ---- rgb = sigmoid(h3 @ Wc3[64,3]) ----
    float r0 = 0.f, r1 = 0.f, r2 = 0.f;
#pragma unroll
    for (int i = 0; i < 64; i++) {
        float f = h3[i];
        r0 += f * sC3[i * 3 + 0];
        r1 += f * sC3[i * 3 + 1];
        r2 += f * sC3[i * 3 + 2];
    }

    float4 res;
    res.x = 1.0f / (1.0f + expf(-r0));
    res.y = 1.0f / (1.0f + expf(-r1));
    res.z = 1.0f / (1.0f + expf(-r2));
    res.w = density;
    *(float4*)(outp + 4 * n) = res;
}

// ---------------------------------------------------------------------------
// Launch
// ---------------------------------------------------------------------------
extern "C" void kernel_launch(void* const* d_in, const int* in_sizes, int n_in,
                              void* d_out, int out_size) {
    const float* pts  = (const float*)d_in[0];
    const float* dirs = (const float*)d_in[1];
    const float* ts   = (const float*)d_in[2];
    const float* yl0 = (const float*)d_in[3];  const float* yh0 = (const float*)d_in[4];
    const float* yl1 = (const float*)d_in[5];  const float* yh1 = (const float*)d_in[6];
    const float* yl2 = (const float*)d_in[7];  const float* yh2 = (const float*)d_in[8];
    const float* yl3 = (const float*)d_in[9];  const float* yh3 = (const float*)d_in[10];
    const float* yl4 = (const float*)d_in[11]; const float* yh4 = (const float*)d_in[12];
    const float* yl5 = (const float*)d_in[13]; const float* yh5 = (const float*)d_in[14];
    const float* Wsig1 = (const float*)d_in[15];
    const float* Wsig2 = (const float*)d_in[16];
    const float* Wc1   = (const float*)d_in[17];
    const float* Wc2   = (const float*)d_in[18];
    const float* Wc3   = (const float*)d_in[19];

    idwt_all<<<2736, 256>>>(yl0, yh0, yl1, yh1, yl2, yh2,
                            yl3, yh3, yl4, yh4, yl5, yh5);

    size_t dyn = 4 * WARPBUF * sizeof(float);   // 34.5 KB dynamic
    wf_gather<<<NSAMP / 128, 128, dyn>>>(pts, ts);

    wf_mlp<<<NSAMP / 128, 128>>>(dirs, Wsig1, Wsig2, Wc1, Wc2, Wc3,
                                 (float*)d_out);
}

// round 11
// speedup vs baseline: 1.2019x; 1.0174x over previous
#include <cuda_runtime.h>
#include <cuda_fp16.h>
#include <math.h>

// ---------------------------------------------------------------------------
// Problem constants
// ---------------------------------------------------------------------------
#define NSAMP    524288      // 8192 rays * 64 samples

// combos: (0,1) (0,2) (0,3) (1,2) (1,3) (2,3)
// widths: 64,64,50,64,50,50  ->  W2: 128,128,100,128,100,100
// Interleaved plane-pair layout per combo: [Y][X][C=32][2] = (hi, lo), fp16.
#define TOTAL_PLANE_ELEMS 5603328   // halves: 11.2 MB

__device__ __half  g_planes[TOTAL_PLANE_ELEMS];
__device__ unsigned g_featsp[32 * NSAMP];       // packed half2 feature pairs, 67 MB

typedef unsigned long long ull;

// ---------------------------------------------------------------------------
// Packed dual-fp32 helpers (sm_100 f32x2 pipe; IEEE-identical per half)
// ---------------------------------------------------------------------------
__device__ __forceinline__ ull pack2(float f) {
    ull r;
    asm("mov.b64 %0, {%1, %1};" : "=l"(r) : "f"(f));
    return r;
}
__device__ __forceinline__ void ffma2(ull& d, ull a, ull b) {
    asm("fma.rn.f32x2 %0, %1, %2, %0;" : "+l"(d) : "l"(a), "l"(b));
}
__device__ __forceinline__ void mul2(ull& d, ull a, ull b) {
    asm("mul.rn.f32x2 %0, %1, %2;" : "=l"(d) : "l"(a), "l"(b));
}
__device__ __forceinline__ void unpack2(ull v, float& lo, float& hi) {
    asm("mov.b64 {%0, %1}, %2;" : "=f"(lo), "=f"(hi) : "l"(v));
}
// half2 (packed in u32) -> packed f32x2 in u64
__device__ __forceinline__ ull h2f2(unsigned v) {
    __half2 h = *(__half2*)&v;
    float2 f = __half22float2(h);
    ull r;
    asm("mov.b64 %0, {%1, %2};" : "=l"(r) : "f"(f.x), "f"(f.y));
    return r;
}

// ---------------------------------------------------------------------------
// IDWT precompute, all 6 combos in one kernel; writes fp16 (hi,lo) pairs.
// ---------------------------------------------------------------------------
template <int W, int W2, int OFF>
__device__ __forceinline__ void idwt_body(const float* __restrict__ yl,
                                          const float* __restrict__ yh,
                                          int idx) {
    if (idx >= 32 * 64 * W) return;

    int j0   = idx % W;
    int rest = idx / W;
    int i0   = rest & 63;
    int c    = rest >> 6;

    float a  = yl[(c * 64 + i0) * W + j0];
    float lh = yh[((c * 3 + 0) * 64 + i0) * W + j0];
    float hl = yh[((c * 3 + 1) * 64 + i0) * W + j0];
    float hh = yh[((c * 3 + 2) * 64 + i0) * W + j0];

    float ee = 0.5f * (a + lh + hl + hh);
    float eo = 0.5f * (a + lh - hl - hh);
    float oe = 0.5f * (a - lh + hl - hh);
    float oo = 0.5f * (a - lh - hl + hh);
    float lo = 0.5f * a;

    int fi = OFF + ((2 * i0) * W2 + 2 * j0) * 64 + 2 * c;   // element index
    __half* gp = g_planes;
    *(__half2*)(gp + fi)                = __floats2half2_rn(ee, lo);
    *(__half2*)(gp + fi + 64)           = __floats2half2_rn(eo, lo);
    *(__half2*)(gp + fi + W2 * 64)      = __floats2half2_rn(oe, lo);
    *(__half2*)(gp + fi + W2 * 64 + 64) = __floats2half2_rn(oo, lo);
}

__global__ __launch_bounds__(256) void idwt_all(
    const float* __restrict__ yl0, const float* __restrict__ yh0,
    const float* __restrict__ yl1, const float* __restrict__ yh1,
    const float* __restrict__ yl2, const float* __restrict__ yh2,
    const float* __restrict__ yl3, const float* __restrict__ yh3,
    const float* __restrict__ yl4, const float* __restrict__ yh4,
    const float* __restrict__ yl5, const float* __restrict__ yh5) {
    int b = blockIdx.x;
    int t = threadIdx.x;
    if      (b <  512) idwt_body<64, 128,       0>(yl0, yh0, (b       ) * 256 + t);
    else if (b < 1024) idwt_body<64, 128, 1048576>(yl1, yh1, (b -  512) * 256 + t);
    else if (b < 1424) idwt_body<50, 100, 2097152>(yl2, yh2, (b - 1024) * 256 + t);
    else if (b < 1936) idwt_body<64, 128, 2916352>(yl3, yh3, (b - 1424) * 256 + t);
    else if (b < 2336) idwt_body<50, 100, 3964928>(yl4, yh4, (b - 1936) * 256 + t);
    else               idwt_body<50, 100, 4784128>(yl5, yh5, (b - 2336) * 256 + t);
}

// ---------------------------------------------------------------------------
// Gather helpers.
// Offset encoding: bits[0:24) = OFF + (y0*W2+x0)*64 (element units),
//                  bit 24 = (x1>x0), bit 25 = (y1>y0).
// ---------------------------------------------------------------------------
template <int W2, int OFF, int J, int K>
__device__ __forceinline__ void prep(const float p4[4], int& oenc,
                                     float& wy, float& wx) {
    float y = (p4[J] + 1.0f) * 0.5f * 127.0f;
    float x = (p4[K] + 1.0f) * 0.5f * (float)(W2 - 1);

    float yf = fminf(fmaxf(floorf(y), 0.0f), 127.0f);
    float xf = fminf(fmaxf(floorf(x), 0.0f), (float)(W2 - 1));
    int y0 = (int)yf, x0 = (int)xf;
    int y1 = min(y0 + 1, 127);
    int x1 = min(x0 + 1, W2 - 1);
    wy = fminf(fmaxf(y - yf, 0.0f), 1.0f);
    wx = fminf(fmaxf(x - xf, 0.0f), 1.0f);

    oenc = (OFF + (y0 * W2 + x0) * 64)
         | ((x1 > x0) ? (1 << 24) : 0)
         | ((y1 > y0) ? (1 << 25) : 0);
}

template <int DYC>   // DYC = W2*64 (element units)
__device__ __forceinline__ void samp(int oenc, float wy, float wx,
                                     int lane2, ull& prod) {
    int base = (oenc & 0xFFFFFF) + lane2;
    int dx = ((oenc >> 24) & 1) << 6;
    int dy = (oenc & (1 << 25)) ? DYC : 0;

    float om_y = 1.0f - wy, om_x = 1.0f - wx;
    ull w00 = pack2(om_y * om_x);
    ull w01 = pack2(om_y * wx);
    ull w10 = pack2(wy * om_x);
    ull w11 = pack2(wy * wx);

    const __half* gp = g_planes;
    unsigned v00 = *(const unsigned*)(gp + base);
    unsigned v01 = *(const unsigned*)(gp + base + dx);
    unsigned v10 = *(const unsigned*)(gp + base + dy);
    unsigned v11 = *(const unsigned*)(gp + base + dy + dx);

    ull acc = 0ull;
    ffma2(acc, w00, h2f2(v00));
    ffma2(acc, w01, h2f2(v01));
    ffma2(acc, w10, h2f2(v10));
    ffma2(acc, w11, h2f2(v11));
    mul2(prod, prod, acc);
}

// ---------------------------------------------------------------------------
// Kernel A: gather -> packed half2 feature scratch. 128 thr/blk.
// ---------------------------------------------------------------------------
#define TSTRIDE 69
#define WARPBUF (32 * TSTRIDE)   // 2208 floats per warp

__global__ __launch_bounds__(128) void wf_gather(
    const float* __restrict__ pts, const float* __restrict__ ts) {

    extern __shared__ float wfbuf[];

    int lane = threadIdx.x & 31;
    int warp = threadIdx.x >> 5;
    int lane2 = 2 * lane;
    int n = blockIdx.x * 128 + threadIdx.x;

    float p4[4];
    p4[0] = pts[3*n + 0];
    p4[1] = pts[3*n + 1];
    p4[2] = pts[3*n + 2];
    p4[3] = ts[n >> 6] * 2.0f - 1.0f;

    int   oe0, oe1, oe2, oe3, oe4, oe5;
    float wy0, wy1, wy2, wy3, wy4, wy5;
    float wx0, wx1, wx2, wx3, wx4, wx5;
    prep<128,       0, 0, 1>(p4, oe0, wy0, wx0);
    prep<128, 1048576, 0, 2>(p4, oe1, wy1, wx1);
    prep<100, 2097152, 0, 3>(p4, oe2, wy2, wx2);
    prep<128, 2916352, 1, 2>(p4, oe3, wy3, wx3);
    prep<100, 3964928, 1, 3>(p4, oe4, wy4, wx4);
    prep<100, 4784128, 2, 3>(p4, oe5, wy5, wx5);

    float* wf = wfbuf + warp * WARPBUF;

#pragma unroll 1
    for (int s = 0; s < 32; s++) {
        ull prod = pack2(1.0f);

#define DO_COMBO(OE, WY, WX, DYC)                                  \
        {                                                          \
            int   o  = __shfl_sync(0xffffffffu, OE, s);            \
            float a_ = __shfl_sync(0xffffffffu, WY, s);            \
            float b_ = __shfl_sync(0xffffffffu, WX, s);            \
            samp<DYC>(o, a_, b_, lane2, prod);                     \
        }
        DO_COMBO(oe0, wy0, wx0, 8192)
        DO_COMBO(oe1, wy1, wx1, 8192)
        DO_COMBO(oe2, wy2, wx2, 6400)
        DO_COMBO(oe3, wy3, wx3, 8192)
        DO_COMBO(oe4, wy4, wx4, 6400)
        DO_COMBO(oe5, wy5, wx5, 6400)
#undef DO_COMBO

        float fh, fl;
        unpack2(prod, fh, fl);
        wf[s * TSTRIDE + lane]      = fh;
        wf[s * TSTRIDE + 34 + lane] = fl;
    }
    __syncwarp();

    // Pack feature pairs to half2 and store coalesced (feature-pair-major).
    // f[j] = my[j] for j<32 (hi), my[j+2] for j>=32 (lo).
    const float* my = wf + lane * TSTRIDE;
#pragma unroll
    for (int q = 0; q < 16; q++) {
        __half2 hp = __floats2half2_rn(my[2*q], my[2*q + 1]);
        g_featsp[q * NSAMP + n] = *(unsigned*)&hp;
    }
#pragma unroll
    for (int q = 16; q < 32; q++) {
        __half2 hp = __floats2half2_rn(my[2*q + 2], my[2*q + 3]);
        g_featsp[q * NSAMP + n] = *(unsigned*)&hp;
    }
}

// ---------------------------------------------------------------------------
// Kernel B: MLP chain with packed f32x2 FFMA. Static smem weights (44.75 KB).
// (R6 full-layer form — best measured variant.)
// ---------------------------------------------------------------------------
__global__ __launch_bounds__(128) void wf_mlp(
    const float* __restrict__ dirs,
    const float* __restrict__ Wsig1, const float* __restrict__ Wsig2,
    const float* __restrict__ Wc1, const float* __restrict__ Wc2,
    const float* __restrict__ Wc3, float* __restrict__ outp) {

    __shared__ __align__(16) float sW1[64 * 64];
    __shared__ __align__(16) float sW2[64 * 16];
    __shared__ __align__(16) float sC1[32 * 64];
    __shared__ __align__(16) float sC2[64 * 64];
    __shared__ float sC3[64 * 3];

    for (int i = threadIdx.x; i < 64*64; i += 128) sW1[i] = Wsig1[i];
    for (int i = threadIdx.x; i < 64*16; i += 128) sW2[i] = Wsig2[i];
    for (int i = threadIdx.x; i < 31*64; i += 128) sC1[i] = Wc1[i];
    for (int i = threadIdx.x; i < 64*64; i += 128) sC2[i] = Wc2[i];
    for (int i = threadIdx.x; i < 64*3;  i += 128) sC3[i] = Wc3[i];
    __syncthreads();

    int n = blockIdx.x * 128 + threadIdx.x;

    // Coalesced packed-half2 feature loads.
    float fv[64];
#pragma unroll
    for (int q = 0; q < 32; q++) {
        unsigned v = g_featsp[q * NSAMP + n];
        __half2 h = *(__half2*)&v;
        float2 f = __half22float2(h);
        fv[2*q]     = f.x;
        fv[2*q + 1] = f.y;
    }

    // ---- MLP1: h = relu(fv @ Wsig1[64,64]) ----
    float h[64];
    {
        ull acc[32];
#pragma unroll
        for (int k = 0; k < 32; k++) acc[k] = 0ull;
#pragma unroll
        for (int i = 0; i < 64; i++) {
            ull fp = pack2(fv[i]);
            const ulonglong2* wrow = (const ulonglong2*)(sW1 + i * 64);
#pragma unroll
            for (int og = 0; og < 16; og++) {
                ulonglong2 w = wrow[og];
                ffma2(acc[2*og],     fp, w.x);
                ffma2(acc[2*og + 1], fp, w.y);
            }
        }
#pragma unroll
        for (int k = 0; k < 32; k++) {
            float lo, hi;
            unpack2(acc[k], lo, hi);
            h[2*k]   = fmaxf(lo, 0.f);
            h[2*k+1] = fmaxf(hi, 0.f);
        }
    }

    // ---- out = h @ Wsig2[64,16] ----
    float ov[16];
    {
        ull acc[8];
#pragma unroll
        for (int k = 0; k < 8; k++) acc[k] = 0ull;
#pragma unroll
        for (int i = 0; i < 64; i++) {
            ull fp = pack2(h[i]);
            const ulonglong2* wrow = (const ulonglong2*)(sW2 + i * 16);
#pragma unroll
            for (int og = 0; og < 4; og++) {
                ulonglong2 w = wrow[og];
                ffma2(acc[2*og],     fp, w.x);
                ffma2(acc[2*og + 1], fp, w.y);
            }
        }
#pragma unroll
        for (int k = 0; k < 8; k++) unpack2(acc[k], ov[2*k], ov[2*k+1]);
    }
    float density = expf(fminf(fmaxf(ov[15], -15.0f), 15.0f));

    // ---- SH degree-4 encoding ----
    int r = n >> 6;
    float dxv = dirs[3*r + 0], dyv = dirs[3*r + 1], dzv = dirs[3*r + 2];
    float inv = rsqrtf(dxv*dxv + dyv*dyv + dzv*dzv);
    float X = dxv * inv, Y = dyv * inv, Z = dzv * inv;
    float xx = X * X, yy = Y * Y, zz = Z * Z;

    float ci[31];
    ci[0]  = 0.28209479177387814f;
    ci[1]  = -0.4886025119029199f * Y;
    ci[2]  = 0.4886025119029199f * Z;
    ci[3]  = -0.4886025119029199f * X;
    ci[4]  = 1.0925484305920792f * X * Y;
    ci[5]  = -1.0925484305920792f * Y * Z;
    ci[6]  = 0.31539156525252005f * (3.0f * zz - 1.0f);
    ci[7]  = -1.0925484305920792f * X * Z;
    ci[8]  = 0.5462742152960396f * (xx - yy);
    ci[9]  = -0.5900435899266435f * Y * (3.0f * xx - yy);
    ci[10] = 2.890611442640554f * X * Y * Z;
    ci[11] = -0.4570457994644658f * Y * (5.0f * zz - 1.0f);
    ci[12] = 0.3731763325901154f * Z * (5.0f * zz - 3.0f);
    ci[13] = -0.4570457994644658f * X * (5.0f * zz - 1.0f);
    ci[14] = 1.445305721320277f * Z * (xx - yy);
    ci[15] = -0.5900435899266435f * X * (xx - 3.0f * yy);
#pragma unroll
    for (int g = 0; g < 15; g++) ci[16 + g] = ov[g];

    // ---- h2 = relu(ci @ Wc1[31,64]) ----
    float h2[64];
    {
        ull acc[32];
#pragma unroll
        for (int k = 0; k < 32; k++) acc[k] = 0ull;
#pragma unroll
        for (int i = 0; i < 31; i++) {
            ull fp = pack2(ci[i]);
            const ulonglong2* wrow = (const ulonglong2*)(sC1 + i * 64);
#pragma unroll
            for (int og = 0; og < 16; og++) {
                ulonglong2 w = wrow[og];
                ffma2(acc[2*og],     fp, w.x);
                ffma2(acc[2*og + 1], fp, w.y);
            }
        }
#pragma unroll
        for (int k = 0; k < 32; k++) {
            float lo, hi;
            unpack2(acc[k], lo, hi);
            h2[2*k]   = fmaxf(lo, 0.f);
            h2[2*k+1] = fmaxf(hi, 0.f);
        }
    }

    // ---- h3 = relu(h2 @ Wc2[64,64]) ----
    float h3[64];
    {
        ull acc[32];
#pragma unroll
        for (int k = 0; k < 32; k++) acc[k] = 0ull;
#pragma unroll
        for (int i = 0; i < 64; i++) {
            ull fp = pack2(h2[i]);
            const ulonglong2* wrow = (const ulonglong2*)(sC2 + i * 64);
#pragma unroll
            for (int og = 0; og < 16; og++) {
                ulonglong2 w = wrow[og];
                ffma2(acc[2*og],     fp, w.x);
                ffma2(acc[2*og + 1], fp, w.y);
            }
        }
#pragma unroll
        for (int k = 0; k < 32; k++) {
            float lo, hi;
            unpack2(acc[k], lo, hi);
            h3[2*k]   = fmaxf(lo, 0.f);
            h3[2*k+1] = fmaxf(hi, 0.f);
        }
    }

    // ---- rgb = sigmoid(h3 @ Wc3[64,3]) ----
    float r0 = 0.f, r1 = 0.f, r2 = 0.f;
#pragma unroll
    for (int i = 0; i < 64; i++) {
        float f = h3[i];
        r0 += f * sC3[i * 3 + 0];
        r1 += f * sC3[i * 3 + 1];
        r2 += f * sC3[i * 3 + 2];
    }

    float4 res;
    res.x = 1.0f / (1.0f + expf(-r0));
    res.y = 1.0f / (1.0f + expf(-r1));
    res.z = 1.0f / (1.0f + expf(-r2));
    res.w = density;
    *(float4*)(outp + 4 * n) = res;
}

// ---------------------------------------------------------------------------
// Launch
// ---------------------------------------------------------------------------
extern "C" void kernel_launch(void* const* d_in, const int* in_sizes, int n_in,
                              void* d_out, int out_size) {
    const float* pts  = (const float*)d_in[0];
    const float* dirs = (const float*)d_in[1];
    const float* ts   = (const float*)d_in[2];
    const float* yl0 = (const float*)d_in[3];  const float* yh0 = (const float*)d_in[4];
    const float* yl1 = (const float*)d_in[5];  const float* yh1 = (const float*)d_in[6];
    const float* yl2 = (const float*)d_in[7];  const float* yh2 = (const float*)d_in[8];
    const float* yl3 = (const float*)d_in[9];  const float* yh3 = (const float*)d_in[10];
    const float* yl4 = (const float*)d_in[11]; const float* yh4 = (const float*)d_in[12];
    const float* yl5 = (const float*)d_in[13]; const float* yh5 = (const float*)d_in[14];
    const float* Wsig1 = (const float*)d_in[15];
    const float* Wsig2 = (const float*)d_in[16];
    const float* Wc1   = (const float*)d_in[17];
    const float* Wc2   = (const float*)d_in[18];
    const float* Wc3   = (const float*)d_in[19];

    idwt_all<<<2736, 256>>>(yl0, yh0, yl1, yh1, yl2, yh2,
                            yl3, yh3, yl4, yh4, yl5, yh5);

    size_t dyn = 4 * WARPBUF * sizeof(float);   // 34.5 KB dynamic
    wf_gather<<<NSAMP / 128, 128, dyn>>>(pts, ts);

    wf_mlp<<<NSAMP / 128, 128>>>(dirs, Wsig1, Wsig2, Wc1, Wc2, Wc3,
                                 (float*)d_out);
}